// round 5
// baseline (speedup 1.0000x reference)
#include <cuda_runtime.h>
#include <math.h>

#define VOCABN 30000
#define DN 100
#define RN 150
#define RWN 50
#define SN 50
#define CN 20
#define BN 256
#define LN 512

// Precomputed tables / folded constants (static device memory — allowed).
__device__ float g_Tv[VOCABN * RN];    // blended V embedding per vocab id
__device__ float g_Trw[VOCABN * SN];   // (Tv*Cvs)@Wrs1 + bs1 per vocab id
__device__ float g_Cvs[RN];            // sum_c C_embed
__device__ float g_wild[SN * SN];      // wildcard transition matrix [s][t]
__device__ float g_S2cT[RN * SN];      // S2[t][r]*Cvs[r], stored [r][t]
__device__ float g_SC[CN * 200];       // [c][0:150]=C_embed*u, [c][150:200]=C_w*uw

// ---------------------------------------------------------------------------
// k0: fold step-invariant constants.
// ---------------------------------------------------------------------------
__global__ void k0_const(const float* __restrict__ C_embed,
                         const float* __restrict__ C_w,
                         const float* __restrict__ S1w,
                         const float* __restrict__ S2w,
                         const float* __restrict__ WW,
                         const float* __restrict__ hT,
                         const float* __restrict__ S2) {
    __shared__ float cvs[RN], cw[RWN], u[RN], uw[RWN];
    int t = threadIdx.x;  // 256 threads
    if (t < RN) {
        float s = 0.f;
        #pragma unroll
        for (int c = 0; c < CN; c++) s += C_embed[c * RN + t];
        cvs[t] = s;
        g_Cvs[t] = s;
        float su = 0.f;
        #pragma unroll
        for (int s2 = 0; s2 < SN; s2++) su += hT[s2] * S2[s2 * RN + t];
        u[t] = su;
    }
    if (t < RWN) {
        float s = 0.f;
        #pragma unroll
        for (int c = 0; c < CN; c++) s += C_w[c * RWN + t];
        cw[t] = s;
        float su = 0.f;
        #pragma unroll
        for (int s2 = 0; s2 < SN; s2++) su += hT[s2] * S2w[s2 * RWN + t];
        uw[t] = su;
    }
    __syncthreads();
    // wild[s][t] = sum_rw S1w[s][rw]*cw[rw]*S2w[t][rw] + WW[s][t]
    for (int idx = t; idx < SN * SN; idx += blockDim.x) {
        int s = idx / SN, tt = idx % SN;
        float acc = WW[idx];
        #pragma unroll
        for (int r = 0; r < RWN; r++)
            acc += S1w[s * RWN + r] * cw[r] * S2w[tt * RWN + r];
        g_wild[idx] = acc;
    }
    // S2cT[r][t] = S2[t][r] * cvs[r]
    for (int idx = t; idx < RN * SN; idx += blockDim.x) {
        int r = idx / SN, tt = idx % SN;
        g_S2cT[idx] = S2[tt * RN + r] * cvs[r];
    }
    // merged score matrix
    for (int idx = t; idx < CN * 200; idx += blockDim.x) {
        int c = idx / 200, i = idx % 200;
        g_SC[idx] = (i < RN) ? C_embed[c * RN + i] * u[i]
                             : C_w[c * RWN + (i - RN)] * uw[i - RN];
    }
}

// ---------------------------------------------------------------------------
// k1: per-vocab tables Tv, Trw.  One vocab row per block (160 threads).
// ---------------------------------------------------------------------------
__global__ void k1_tables(const float* __restrict__ W_embed,
                          const float* __restrict__ embed_r,
                          const float* __restrict__ V_embed,
                          const float* __restrict__ beta,
                          const float* __restrict__ Wrs1,
                          const float* __restrict__ bs1) {
    __shared__ float w[DN];
    __shared__ float q[RN];
    int v = blockIdx.x;
    int t = threadIdx.x;  // 160
    if (t < DN) w[t] = W_embed[v * DN + t];
    __syncthreads();
    if (t < RN) {
        float acc = 0.f;
        #pragma unroll 5
        for (int d = 0; d < DN; d++) acc += w[d] * embed_r[d * RN + t];
        float e = tanhf(acc);
        float b = beta[t];
        float tv = V_embed[v * RN + t] * b + e * (1.f - b);
        g_Tv[v * RN + t] = tv;
        q[t] = tv * g_Cvs[t];
    }
    __syncthreads();
    if (t < SN) {
        float acc = bs1[t];
        #pragma unroll 5
        for (int r = 0; r < RN; r++) acc += q[r] * Wrs1[r * SN + t];
        g_Trw[v * SN + t] = acc;
    }
}

// ---------------------------------------------------------------------------
// k2: the sequential recurrence. 128 CTAs, 2 batch chains per CTA packed into
// float2 lanes. blockDim = 288. All weights register-resident per thread.
//
// Shared act layout (float2, per chain pair):
//   act[0..49]    = h                (state)
//   act[50..199]  = p  = (h@S1)*Tv[tok]
//   act[200..249] = aw = h@S1_w
//
// Phase-1 roles (threads 0..249): 50-length dots over h.
//   t<150   : a[t]  -> p[t] = a*Tv          (also gathers Tv pair)
//   150..199: aw[t-150]
//   200..249: gate pre-act -> sigmoid -> gz  (also gathers Trw pair)
// Phase-2 roles (threads 0..279): 50-length chunk dots over act.
//   t<200   : h_new[t>>2], chunk t&3: 3x S2cT chunks over p, 1x wild over h
//   200..279: score[c=(t-200)>>2], chunk over merged [p|aw] window
// Combine (threads 0..71): 4-way partial sums, gate blend, score affine,
//   output store, next-token prefetch.
// ---------------------------------------------------------------------------
__global__ void __launch_bounds__(288)
k2_recur(const int* __restrict__ tokens,
         const float* __restrict__ S1,
         const float* __restrict__ S1w,
         const float* __restrict__ Wss1,
         const float* __restrict__ h0,
         const float* __restrict__ prio_a,
         const float* __restrict__ prio_b,
         float* __restrict__ out) {
    __shared__ float2 act[250];
    __shared__ float2 gz[SN];
    __shared__ float2 part[280];
    __shared__ int s_tok[2];

    int t = threadIdx.x;
    int b0 = blockIdx.x * 2;
    int b1 = b0 + 1;

    // ---- load register-resident weights (once) ----
    float wA[50];
    float wB[50];
    int aoff = 0;

    if (t < 150) {
        #pragma unroll
        for (int k = 0; k < 50; k++) wA[k] = S1[k * RN + t];
    } else if (t < 200) {
        int rw = t - 150;
        #pragma unroll
        for (int k = 0; k < 50; k++) wA[k] = S1w[k * RWN + rw];
    } else if (t < 250) {
        int s2 = t - 200;
        #pragma unroll
        for (int k = 0; k < 50; k++) wA[k] = Wss1[k * SN + s2];
    }

    if (t < 200) {
        int tt = t >> 2, q = t & 3;
        if (q < 3) {
            #pragma unroll
            for (int k = 0; k < 50; k++) wB[k] = g_S2cT[(q * 50 + k) * SN + tt];
            aoff = 50 + q * 50;
        } else {
            #pragma unroll
            for (int k = 0; k < 50; k++) wB[k] = g_wild[k * SN + tt];
            aoff = 0;
        }
    } else if (t < 280) {
        int m = t - 200;
        int c = m >> 2, q = m & 3;
        #pragma unroll
        for (int k = 0; k < 50; k++) wB[k] = g_SC[c * 200 + q * 50 + k];
        aoff = 50 + q * 50;
    }

    float pa = 0.f, pb = 0.f;
    if (t >= 50 && t < 70) { pa = prio_a[t - 50]; pb = prio_b[t - 50]; }

    // ---- init state + first tokens ----
    if (t < SN) { float h = h0[t]; act[t] = make_float2(h, h); }
    if (t == 70) s_tok[0] = tokens[b0 * LN];
    if (t == 71) s_tok[1] = tokens[b1 * LN];
    __syncthreads();

    for (int l = 0; l < LN; l++) {
        int tok0 = s_tok[0];
        int tok1 = s_tok[1];

        // ---------------- phase 1 ----------------
        if (t < 250) {
            float2 tv, trw;
            if (t < 150) {
                tv.x = g_Tv[tok0 * RN + t];
                tv.y = g_Tv[tok1 * RN + t];
            }
            if (t >= 200) {
                int s2 = t - 200;
                trw.x = g_Trw[tok0 * SN + s2];
                trw.y = g_Trw[tok1 * SN + s2];
            }
            float ax = 0.f, ay = 0.f, bx = 0.f, by = 0.f;
            #pragma unroll
            for (int k = 0; k < 50; k += 2) {
                float2 h1 = act[k];
                float2 h2 = act[k + 1];
                ax += wA[k] * h1.x;     ay += wA[k] * h1.y;
                bx += wA[k + 1] * h2.x; by += wA[k + 1] * h2.y;
            }
            float accx = ax + bx, accy = ay + by;
            if (t < 150) {
                act[50 + t] = make_float2(accx * tv.x, accy * tv.y);
            } else if (t < 200) {
                act[200 + (t - 150)] = make_float2(accx, accy);
            } else {
                int s2 = t - 200;
                float zx = 1.f / (1.f + expf(-(accx + trw.x)));
                float zy = 1.f / (1.f + expf(-(accy + trw.y)));
                gz[s2] = make_float2(zx, zy);
            }
        }
        __syncthreads();

        // ---------------- phase 2 ----------------
        if (t < 280) {
            float ax = 0.f, ay = 0.f, bx = 0.f, by = 0.f;
            #pragma unroll
            for (int k = 0; k < 50; k += 2) {
                float2 h1 = act[aoff + k];
                float2 h2 = act[aoff + k + 1];
                ax += wB[k] * h1.x;     ay += wB[k] * h1.y;
                bx += wB[k + 1] * h2.x; by += wB[k + 1] * h2.y;
            }
            part[t] = make_float2(ax + bx, ay + by);
        }
        __syncthreads();

        // ---------------- combine ----------------
        if (t < 50) {
            float2 p0 = part[4 * t], p1 = part[4 * t + 1];
            float2 p2 = part[4 * t + 2], p3 = part[4 * t + 3];
            float hnx = p0.x + p1.x + p2.x + p3.x;
            float hny = p0.y + p1.y + p2.y + p3.y;
            float2 z = gz[t];
            float2 ho = act[t];
            act[t] = make_float2(z.x * hnx + (1.f - z.x) * ho.x,
                                 z.y * hny + (1.f - z.y) * ho.y);
        } else if (t < 70) {
            int c = t - 50;
            float2 p0 = part[200 + 4 * c], p1 = part[200 + 4 * c + 1];
            float2 p2 = part[200 + 4 * c + 2], p3 = part[200 + 4 * c + 3];
            float sx = p0.x + p1.x + p2.x + p3.x;
            float sy = p0.y + p1.y + p2.y + p3.y;
            out[(b0 * LN + l) * CN + c] = sx * pa + pb;
            out[(b1 * LN + l) * CN + c] = sy * pa + pb;
        } else if (t == 70) {
            if (l + 1 < LN) s_tok[0] = tokens[b0 * LN + l + 1];
        } else if (t == 71) {
            if (l + 1 < LN) s_tok[1] = tokens[b1 * LN + l + 1];
        }
        __syncthreads();
    }
}

// ---------------------------------------------------------------------------
// Launch. Input order (metadata): tokens, W_embed, embed_r, V_embed, C_embed,
// S1, S2, S1_w, S2_w, C_w, WW, h0, hT, beta_vec, Wss1, Wrs1, bs1, prio_a, prio_b
// ---------------------------------------------------------------------------
extern "C" void kernel_launch(void* const* d_in, const int* in_sizes, int n_in,
                              void* d_out, int out_size) {
    const int*   tokens  = (const int*)  d_in[0];
    const float* W_embed = (const float*)d_in[1];
    const float* embed_r = (const float*)d_in[2];
    const float* V_embed = (const float*)d_in[3];
    const float* C_embed = (const float*)d_in[4];
    const float* S1      = (const float*)d_in[5];
    const float* S2      = (const float*)d_in[6];
    const float* S1_w    = (const float*)d_in[7];
    const float* S2_w    = (const float*)d_in[8];
    const float* C_w     = (const float*)d_in[9];
    const float* WW      = (const float*)d_in[10];
    const float* h0      = (const float*)d_in[11];
    const float* hT      = (const float*)d_in[12];
    const float* beta    = (const float*)d_in[13];
    const float* Wss1    = (const float*)d_in[14];
    const float* Wrs1    = (const float*)d_in[15];
    const float* bs1     = (const float*)d_in[16];
    const float* prio_a  = (const float*)d_in[17];
    const float* prio_b  = (const float*)d_in[18];
    float* out = (float*)d_out;

    k0_const<<<1, 256>>>(C_embed, C_w, S1_w, S2_w, WW, hT, S2);
    k1_tables<<<VOCABN, 160>>>(W_embed, embed_r, V_embed, beta, Wrs1, bs1);
    k2_recur<<<BN / 2, 288>>>(tokens, S1, S1_w, Wss1, h0, prio_a, prio_b, out);
}